// round 3
// baseline (speedup 1.0000x reference)
#include <cuda_runtime.h>
#include <cuda_bf16.h>
#include <math.h>

#define MAXN 100000
#define MAXE 1200000
#define D    64
#define HID  128
#define C    40

// ---------------- device scratch ----------------
__device__ int   d_deg[MAXN];
__device__ int   d_cursor[MAXN];
__device__ int   d_rowptr[MAXN + 1];
__device__ int   d_col[MAXE];
__device__ float d_y[(size_t)MAXN * C];           // 16 MB

// packed f32x2 helpers (sm_100+)
__device__ __forceinline__ unsigned long long pk2(float x, float y) {
    unsigned long long r;
    asm("mov.b64 %0, {%1,%2};" : "=l"(r) : "f"(x), "f"(y));
    return r;
}
#define FMA2(d, a, b, c) asm("fma.rn.f32x2 %0, %1, %2, %3;" : "=l"(d) : "l"(a), "l"(b), "l"(c))
__device__ __forceinline__ void upk2(float& x, float& y, unsigned long long v) {
    asm("mov.b64 {%0,%1}, %2;" : "=f"(x), "=f"(y) : "l"(v));
}

// ---------------- CSR build ----------------
__global__ void k_init(int n) {
    int i = blockIdx.x * blockDim.x + threadIdx.x;
    if (i < n) { d_deg[i] = 0; d_cursor[i] = 0; }
}

__global__ void k_count(const int2* __restrict__ adj, int e) {
    int i = blockIdx.x * blockDim.x + threadIdx.x;
    if (i < e) atomicAdd(&d_deg[adj[i].y], 1);
}

__global__ void k_scan(int n) {
    __shared__ int ssum[1024];
    int tid = threadIdx.x;
    int chunk = (n + 1023) >> 10;
    int s0 = tid * chunk;
    int s1 = s0 + chunk; if (s1 > n) s1 = n;
    int s = 0;
    for (int i = s0; i < s1; i++) s += d_deg[i];
    ssum[tid] = s;
    __syncthreads();
    for (int off = 1; off < 1024; off <<= 1) {
        int v = (tid >= off) ? ssum[tid - off] : 0;
        __syncthreads();
        ssum[tid] += v;
        __syncthreads();
    }
    int run = (tid == 0) ? 0 : ssum[tid - 1];
    for (int i = s0; i < s1; i++) { d_rowptr[i] = run; run += d_deg[i]; }
    if (tid == 1023) d_rowptr[n] = ssum[1023];
}

__global__ void k_scatter(const int2* __restrict__ adj, int e) {
    int i = blockIdx.x * blockDim.x + threadIdx.x;
    if (i < e) {
        int2 ed = adj[i];
        int p = atomicAdd(&d_cursor[ed.y], 1);
        d_col[d_rowptr[ed.y] + p] = ed.x;
    }
}

// ---------------- fused: agg1 + GEMM1 + ReLU + GEMM2 -> d_y ----------------
// per block: 64 nodes, 256 threads
// smem floats: sW1[64*128] | sW2[128*40] | sAT[64][68] | sX[128][66]
#define SM_W1 0
#define SM_W2 8192
#define SM_AT 13312
#define SM_X  17664
#define SM_TOTAL_F 26112   // 104448 bytes

__global__ void __launch_bounds__(256) k_fused(const float* __restrict__ h,
                                               const float* __restrict__ W1,
                                               const float* __restrict__ b1,
                                               const float* __restrict__ W2,
                                               int n) {
    extern __shared__ float smem[];
    float* sW1 = smem + SM_W1;
    float* sW2 = smem + SM_W2;
    float* sAT = smem + SM_AT;   // [k][node], stride 68 (16B-aligned rows)
    float* sX  = smem + SM_X;    // [hid][node], stride 66 (8B-aligned pairs)
    __shared__ int s_next;

    int tid = threadIdx.x;
    int node0 = blockIdx.x * 64;
    if (tid == 0) s_next = 0;

    // ---- load weights ----
    {
        const float4* W4 = (const float4*)W1;
        float4* s4 = (float4*)sW1;
#pragma unroll
        for (int i = 0; i < 8; i++) s4[tid + i * 256] = W4[tid + i * 256];
        const float4* V4 = (const float4*)W2;
        float4* t4 = (float4*)sW2;
#pragma unroll
        for (int i = 0; i < 5; i++) t4[tid + i * 256] = V4[tid + i * 256];
    }
    __syncthreads();   // s_next + (weights needed later anyway)

    // ---- phase 0: gather-aggregate, warp-per-node with dynamic work stealing ----
    {
        int lane = tid & 31;
        const float2* h2 = (const float2*)h;
        for (;;) {
            int nodeL;
            if (lane == 0) nodeL = atomicAdd(&s_next, 1);
            nodeL = __shfl_sync(0xffffffffu, nodeL, 0);
            if (nodeL >= 64) break;
            int gn = node0 + nodeL;
            float2 acc = make_float2(0.f, 0.f);
            if (gn < n) {
                acc = h2[(size_t)gn * 32 + lane];     // self-loop
                int beg = d_rowptr[gn], end = d_rowptr[gn + 1];
                int j = beg;
                for (; j + 3 < end; j += 4) {
                    int s0 = d_col[j], s1 = d_col[j + 1];
                    int s2 = d_col[j + 2], s3 = d_col[j + 3];
                    float2 v0 = h2[(size_t)s0 * 32 + lane];
                    float2 v1 = h2[(size_t)s1 * 32 + lane];
                    float2 v2 = h2[(size_t)s2 * 32 + lane];
                    float2 v3 = h2[(size_t)s3 * 32 + lane];
                    acc.x += (v0.x + v1.x) + (v2.x + v3.x);
                    acc.y += (v0.y + v1.y) + (v2.y + v3.y);
                }
                for (; j < end; j++) {
                    int s = d_col[j];
                    float2 v = h2[(size_t)s * 32 + lane];
                    acc.x += v.x; acc.y += v.y;
                }
            }
            sAT[(2 * lane) * 68 + nodeL]     = acc.x;
            sAT[(2 * lane + 1) * 68 + nodeL] = acc.y;
        }
    }
    __syncthreads();

    // ---- phase 1: x1 = relu(agg @ W1 + b1), f32x2-packed over output pairs ----
    {
        int ng = tid & 15;    // nodes ng*4 .. +3
        int og = tid >> 4;    // hids  og*8 .. +7 (4 pairs)
        unsigned long long acc2[4][4];
#pragma unroll
        for (int i = 0; i < 4; i++)
#pragma unroll
            for (int jp = 0; jp < 4; jp++) acc2[i][jp] = 0ull;

#pragma unroll
        for (int k = 0; k < D; k++) {
            float4 a4 = *(const float4*)&sAT[k * 68 + ng * 4];
            unsigned long long av2[4] = {pk2(a4.x, a4.x), pk2(a4.y, a4.y),
                                         pk2(a4.z, a4.z), pk2(a4.w, a4.w)};
            float4 w4a = *(const float4*)&sW1[k * HID + og * 8];
            float4 w4b = *(const float4*)&sW1[k * HID + og * 8 + 4];
            unsigned long long wv2[4] = {pk2(w4a.x, w4a.y), pk2(w4a.z, w4a.w),
                                         pk2(w4b.x, w4b.y), pk2(w4b.z, w4b.w)};
#pragma unroll
            for (int i = 0; i < 4; i++)
#pragma unroll
                for (int jp = 0; jp < 4; jp++)
                    FMA2(acc2[i][jp], av2[i], wv2[jp], acc2[i][jp]);
        }

        float bb[8];
#pragma unroll
        for (int j = 0; j < 8; j++) bb[j] = b1[og * 8 + j];

#pragma unroll
        for (int i = 0; i < 4; i++) {
#pragma unroll
            for (int jp = 0; jp < 4; jp++) {
                float lo, hi_;
                upk2(lo, hi_, acc2[i][jp]);
                sX[(og * 8 + 2 * jp) * 66 + (ng * 4 + i)]     = fmaxf(lo + bb[2 * jp], 0.f);
                sX[(og * 8 + 2 * jp + 1) * 66 + (ng * 4 + i)] = fmaxf(hi_ + bb[2 * jp + 1], 0.f);
            }
        }
    }
    __syncthreads();

    // ---- phase 2: y = x1 @ W2, f32x2-packed over output pairs ----
    {
        int og = tid & 3;     // outs og*10 .. +9 (5 pairs)
        int ng = tid >> 2;    // node ng (0..63)
        unsigned long long acc2[5] = {0ull, 0ull, 0ull, 0ull, 0ull};

#pragma unroll 4
        for (int k = 0; k < HID; k++) {
            float a = sX[k * 66 + ng];
            unsigned long long av2 = pk2(a, a);
#pragma unroll
            for (int jj = 0; jj < 5; jj++) {
                unsigned long long w2 =
                    *(const unsigned long long*)&sW2[k * C + og * 10 + 2 * jj];
                FMA2(acc2[jj], av2, w2, acc2[jj]);
            }
        }
        int gn = node0 + ng;
        if (gn < n) {
#pragma unroll
            for (int jj = 0; jj < 5; jj++) {
                float lo, hi_;
                upk2(lo, hi_, acc2[jj]);
                d_y[(size_t)gn * C + og * 10 + 2 * jj]     = lo;
                d_y[(size_t)gn * C + og * 10 + 2 * jj + 1] = hi_;
            }
        }
    }
}

// ---------------- layer-2 aggregation + bias + softmax ----------------
__global__ void k_agg2_softmax(const float* __restrict__ b2, float* __restrict__ out, int n) {
    int w = (blockIdx.x * blockDim.x + threadIdx.x) >> 5;
    int lane = threadIdx.x & 31;
    if (w >= n) return;
    const float* Y = d_y;
    bool hi = (lane < 8);
    float a = Y[(size_t)w * C + lane];
    float b = hi ? Y[(size_t)w * C + 32 + lane] : 0.f;
    int beg = d_rowptr[w], end = d_rowptr[w + 1];
    int j = beg;
    for (; j + 3 < end; j += 4) {
        int s0 = d_col[j], s1 = d_col[j + 1];
        int s2 = d_col[j + 2], s3 = d_col[j + 3];
        float a0 = Y[(size_t)s0 * C + lane];
        float a1 = Y[(size_t)s1 * C + lane];
        float a2 = Y[(size_t)s2 * C + lane];
        float a3 = Y[(size_t)s3 * C + lane];
        a += (a0 + a1) + (a2 + a3);
        if (hi) {
            float b0 = Y[(size_t)s0 * C + 32 + lane];
            float b1v = Y[(size_t)s1 * C + 32 + lane];
            float b2v = Y[(size_t)s2 * C + 32 + lane];
            float b3 = Y[(size_t)s3 * C + 32 + lane];
            b += (b0 + b1v) + (b2v + b3);
        }
    }
    for (; j < end; j++) {
        int s = d_col[j];
        a += Y[(size_t)s * C + lane];
        if (hi) b += Y[(size_t)s * C + 32 + lane];
    }
    a += b2[lane];
    if (hi) b += b2[32 + lane];

    float m = hi ? fmaxf(a, b) : a;
#pragma unroll
    for (int off = 16; off; off >>= 1)
        m = fmaxf(m, __shfl_xor_sync(0xffffffffu, m, off));
    float ea = __expf(a - m);
    float eb = hi ? __expf(b - m) : 0.f;
    float s = ea + eb;
#pragma unroll
    for (int off = 16; off; off >>= 1)
        s += __shfl_xor_sync(0xffffffffu, s, off);
    float inv = 1.f / s;
    out[(size_t)w * C + lane] = ea * inv;
    if (hi) out[(size_t)w * C + 32 + lane] = eb * inv;
}

// ---------------- launch ----------------
extern "C" void kernel_launch(void* const* d_in, const int* in_sizes, int n_in,
                              void* d_out, int out_size) {
    const float* h   = (const float*)d_in[0];
    const int*   adj = (const int*)d_in[1];
    const float* W1  = (const float*)d_in[2];
    const float* b1  = (const float*)d_in[3];
    const float* W2  = (const float*)d_in[4];
    const float* b2  = (const float*)d_in[5];
    float* out = (float*)d_out;

    int n = in_sizes[0] / D;
    int e = in_sizes[1] / 2;
    if (n > MAXN) n = MAXN;
    if (e > MAXE) e = MAXE;

    cudaFuncSetAttribute(k_fused, cudaFuncAttributeMaxDynamicSharedMemorySize,
                         SM_TOTAL_F * (int)sizeof(float));

    k_init<<<(n + 255) / 256, 256>>>(n);
    k_count<<<(e + 255) / 256, 256>>>((const int2*)adj, e);
    k_scan<<<1, 1024>>>(n);
    k_scatter<<<(e + 255) / 256, 256>>>((const int2*)adj, e);

    k_fused<<<(n + 63) / 64, 256, SM_TOTAL_F * sizeof(float)>>>(h, W1, b1, W2, n);
    k_agg2_softmax<<<(n * 32 + 255) / 256, 256>>>(b2, out, n);
}

// round 5
// speedup vs baseline: 1.0261x; 1.0261x over previous
#include <cuda_runtime.h>
#include <cuda_bf16.h>
#include <math.h>

#define MAXN 100000
#define MAXE 1200000
#define D    64
#define HID  128
#define C    40

// ---------------- device scratch ----------------
__device__ int   d_deg[MAXN];
__device__ int   d_cursor[MAXN];
__device__ int   d_rowptr[MAXN + 1];
__device__ int   d_col[MAXE];
__device__ __align__(16) float d_y[(size_t)MAXN * C];   // 16 MB, 16B-aligned for float4

// ---------------- CSR build ----------------
__global__ void k_init(int n) {
    int i = blockIdx.x * blockDim.x + threadIdx.x;
    if (i < n) { d_deg[i] = 0; d_cursor[i] = 0; }
}

__global__ void k_count(const int2* __restrict__ adj, int e) {
    int i = blockIdx.x * blockDim.x + threadIdx.x;
    if (i < e) atomicAdd(&d_deg[adj[i].y], 1);
}

__global__ void k_scan(int n) {
    __shared__ int ssum[1024];
    int tid = threadIdx.x;
    int chunk = (n + 1023) >> 10;
    int s0 = tid * chunk;
    int s1 = s0 + chunk; if (s1 > n) s1 = n;
    int s = 0;
    for (int i = s0; i < s1; i++) s += d_deg[i];
    ssum[tid] = s;
    __syncthreads();
    for (int off = 1; off < 1024; off <<= 1) {
        int v = (tid >= off) ? ssum[tid - off] : 0;
        __syncthreads();
        ssum[tid] += v;
        __syncthreads();
    }
    int run = (tid == 0) ? 0 : ssum[tid - 1];
    for (int i = s0; i < s1; i++) { d_rowptr[i] = run; run += d_deg[i]; }
    if (tid == 1023) d_rowptr[n] = ssum[1023];
}

__global__ void k_scatter(const int2* __restrict__ adj, int e) {
    int i = blockIdx.x * blockDim.x + threadIdx.x;
    if (i < e) {
        int2 ed = adj[i];
        int p = atomicAdd(&d_cursor[ed.y], 1);
        d_col[d_rowptr[ed.y] + p] = ed.x;
    }
}

// ---------------- fused: agg1 + GEMM1 + ReLU + GEMM2 -> d_y ----------------
// smem floats: sW1[64*128]=8192 | sW2[128*40]=5120 | sAT[64][68]=4352 | sX[128][65]=8320
#define SM_W1 0
#define SM_W2 8192
#define SM_AT 13312
#define SM_X  17664
#define SM_TOTAL_F 25984   // 103936 bytes

__global__ void __launch_bounds__(256) k_fused(const float* __restrict__ h,
                                               const float* __restrict__ W1,
                                               const float* __restrict__ b1,
                                               const float* __restrict__ W2,
                                               int n) {
    extern __shared__ float smem[];
    float* sW1 = smem + SM_W1;
    float* sW2 = smem + SM_W2;
    float* sAT = smem + SM_AT;   // [k][node] stride 68 (16B-aligned rows)
    float* sX  = smem + SM_X;    // [hid][node] stride 65 (scalar access only)

    int tid = threadIdx.x;
    int node0 = blockIdx.x * 64;

    // ---- load weights ----
    {
        const float4* W4 = (const float4*)W1;
        float4* s4 = (float4*)sW1;
#pragma unroll
        for (int i = 0; i < 8; i++) s4[tid + i * 256] = W4[tid + i * 256];
        const float4* V4 = (const float4*)W2;
        float4* t4 = (float4*)sW2;
#pragma unroll
        for (int i = 0; i < 5; i++) t4[tid + i * 256] = V4[tid + i * 256];
    }

    // ---- phase 0: gather-aggregate; half-warp x float4, 2 edges/warp-step ----
    {
        int w = tid >> 5, lane = tid & 31;
        int half = lane >> 4;      // 0 or 1
        int q = lane & 15;         // float4 slot within 64-float row
        const float4* h4 = (const float4*)h;
#pragma unroll
        for (int ii = 0; ii < 8; ii++) {
            int nodeL = w * 8 + ii;
            int gn = node0 + nodeL;
            float4 acc = make_float4(0.f, 0.f, 0.f, 0.f);
            if (gn < n) {
                if (half == 0) acc = h4[(size_t)gn * 16 + q];   // self-loop
                int beg = d_rowptr[gn], end = d_rowptr[gn + 1];
                int j = beg;
                for (; j + 3 < end; j += 4) {                    // 4 edges (2/half)
                    int s0 = d_col[j + half];
                    int s1 = d_col[j + 2 + half];
                    float4 v0 = h4[(size_t)s0 * 16 + q];
                    float4 v1 = h4[(size_t)s1 * 16 + q];
                    acc.x += v0.x + v1.x;
                    acc.y += v0.y + v1.y;
                    acc.z += v0.z + v1.z;
                    acc.w += v0.w + v1.w;
                }
                if (j + 1 < end) {                               // 2 edges
                    int s = d_col[j + half];
                    float4 v = h4[(size_t)s * 16 + q];
                    acc.x += v.x; acc.y += v.y; acc.z += v.z; acc.w += v.w;
                    j += 2;
                }
                if (j < end && half == 0) {                      // last odd edge
                    int s = d_col[j];
                    float4 v = h4[(size_t)s * 16 + q];
                    acc.x += v.x; acc.y += v.y; acc.z += v.z; acc.w += v.w;
                }
            }
            acc.x += __shfl_xor_sync(0xffffffffu, acc.x, 16);
            acc.y += __shfl_xor_sync(0xffffffffu, acc.y, 16);
            acc.z += __shfl_xor_sync(0xffffffffu, acc.z, 16);
            acc.w += __shfl_xor_sync(0xffffffffu, acc.w, 16);
            if (half == 0) {
                sAT[(4 * q + 0) * 68 + nodeL] = acc.x;
                sAT[(4 * q + 1) * 68 + nodeL] = acc.y;
                sAT[(4 * q + 2) * 68 + nodeL] = acc.z;
                sAT[(4 * q + 3) * 68 + nodeL] = acc.w;
            }
        }
    }
    __syncthreads();

    // ---- phase 1: x1 = relu(agg @ W1 + b1) -> sX transposed ----
    {
        int ng = tid & 15;
        int og = tid >> 4;
        float acc[4][8];
#pragma unroll
        for (int i = 0; i < 4; i++)
#pragma unroll
            for (int j = 0; j < 8; j++) acc[i][j] = 0.f;

#pragma unroll
        for (int k = 0; k < D; k++) {
            float4 a4 = *(const float4*)&sAT[k * 68 + ng * 4];   // 16B-aligned
            float av[4] = {a4.x, a4.y, a4.z, a4.w};
            float4 w0 = *(const float4*)&sW1[k * HID + og * 8];
            float4 w1 = *(const float4*)&sW1[k * HID + og * 8 + 4];
            float wv[8] = {w0.x, w0.y, w0.z, w0.w, w1.x, w1.y, w1.z, w1.w};
#pragma unroll
            for (int i = 0; i < 4; i++)
#pragma unroll
                for (int j = 0; j < 8; j++) acc[i][j] += av[i] * wv[j];
        }
        float bb[8];
#pragma unroll
        for (int j = 0; j < 8; j++) bb[j] = b1[og * 8 + j];
#pragma unroll
        for (int i = 0; i < 4; i++)
#pragma unroll
            for (int j = 0; j < 8; j++)
                sX[(og * 8 + j) * 65 + (ng * 4 + i)] = fmaxf(acc[i][j] + bb[j], 0.f);
    }
    __syncthreads();

    // ---- phase 2: y = x1 @ W2 ----
    {
        int og = tid & 7;     // outs og*5 .. +4
        int ng = tid >> 3;    // nodes ng*2 .. +1
        float acc[2][5];
#pragma unroll
        for (int i = 0; i < 2; i++)
#pragma unroll
            for (int j = 0; j < 5; j++) acc[i][j] = 0.f;

#pragma unroll 8
        for (int k = 0; k < HID; k++) {
            float av[2];
            av[0] = sX[k * 65 + ng * 2];
            av[1] = sX[k * 65 + ng * 2 + 1];
            float wv[5];
#pragma unroll
            for (int j = 0; j < 5; j++) wv[j] = sW2[k * C + og * 5 + j];
#pragma unroll
            for (int i = 0; i < 2; i++)
#pragma unroll
                for (int j = 0; j < 5; j++) acc[i][j] += av[i] * wv[j];
        }
#pragma unroll
        for (int i = 0; i < 2; i++) {
            int gn = node0 + ng * 2 + i;
            if (gn < n) {
#pragma unroll
                for (int j = 0; j < 5; j++)
                    d_y[(size_t)gn * C + og * 5 + j] = acc[i][j];
            }
        }
    }
}

// ---------------- layer-2 aggregation + bias + softmax (float4, 3 edges/step) ----------------
__global__ void k_agg2_softmax(const float* __restrict__ b2, float* __restrict__ out, int n) {
    int w = (blockIdx.x * blockDim.x + threadIdx.x) >> 5;
    int lane = threadIdx.x & 31;
    if (w >= n) return;

    int g = lane / 10;            // edge group 0..2 (lanes 30,31 idle)
    int q = lane - g * 10;        // float4 slot 0..9
    bool act = (lane < 30);
    const float4* Y4 = (const float4*)d_y;

    float4 acc = make_float4(0.f, 0.f, 0.f, 0.f);
    if (act && g == 0) acc = Y4[(size_t)w * 10 + q];     // self-loop

    int beg = d_rowptr[w], end = d_rowptr[w + 1];
    int j = beg;
    for (; j + 5 < end; j += 6) {                        // 6 edges (2/group)
        if (act) {
            int s0 = d_col[j + g];
            int s1 = d_col[j + 3 + g];
            float4 v0 = Y4[(size_t)s0 * 10 + q];
            float4 v1 = Y4[(size_t)s1 * 10 + q];
            acc.x += v0.x + v1.x;
            acc.y += v0.y + v1.y;
            acc.z += v0.z + v1.z;
            acc.w += v0.w + v1.w;
        }
    }
    if (j + 2 < end) {                                   // 3 edges
        if (act) {
            int s = d_col[j + g];
            float4 v = Y4[(size_t)s * 10 + q];
            acc.x += v.x; acc.y += v.y; acc.z += v.z; acc.w += v.w;
        }
        j += 3;
    }
    int rem = end - j;                                   // 0..2 edges
    if (act && g < rem) {
        int s = d_col[j + g];
        float4 v = Y4[(size_t)s * 10 + q];
        acc.x += v.x; acc.y += v.y; acc.z += v.z; acc.w += v.w;
    }

    // merge 3 groups into lanes 0-9
    acc.x += __shfl_sync(0xffffffffu, acc.x, lane + 10) + __shfl_sync(0xffffffffu, acc.x, lane + 20);
    acc.y += __shfl_sync(0xffffffffu, acc.y, lane + 10) + __shfl_sync(0xffffffffu, acc.y, lane + 20);
    acc.z += __shfl_sync(0xffffffffu, acc.z, lane + 10) + __shfl_sync(0xffffffffu, acc.z, lane + 20);
    acc.w += __shfl_sync(0xffffffffu, acc.w, lane + 10) + __shfl_sync(0xffffffffu, acc.w, lane + 20);

    bool own = (lane < 10);
    if (own) {
        float4 bb;
        bb.x = b2[lane * 4 + 0];
        bb.y = b2[lane * 4 + 1];
        bb.z = b2[lane * 4 + 2];
        bb.w = b2[lane * 4 + 3];
        acc.x += bb.x; acc.y += bb.y; acc.z += bb.z; acc.w += bb.w;
    }
    float m = own ? fmaxf(fmaxf(acc.x, acc.y), fmaxf(acc.z, acc.w)) : -1e30f;
#pragma unroll
    for (int off = 16; off; off >>= 1)
        m = fmaxf(m, __shfl_xor_sync(0xffffffffu, m, off));
    float4 ev;
    ev.x = __expf(acc.x - m);
    ev.y = __expf(acc.y - m);
    ev.z = __expf(acc.z - m);
    ev.w = __expf(acc.w - m);
    float s = own ? (ev.x + ev.y) + (ev.z + ev.w) : 0.f;
#pragma unroll
    for (int off = 16; off; off >>= 1)
        s += __shfl_xor_sync(0xffffffffu, s, off);
    float inv = 1.f / s;
    if (own) {
        float* o = out + (size_t)w * C + lane * 4;
        o[0] = ev.x * inv;
        o[1] = ev.y * inv;
        o[2] = ev.z * inv;
        o[3] = ev.w * inv;
    }
}

// ---------------- launch ----------------
extern "C" void kernel_launch(void* const* d_in, const int* in_sizes, int n_in,
                              void* d_out, int out_size) {
    const float* h   = (const float*)d_in[0];
    const int*   adj = (const int*)d_in[1];
    const float* W1  = (const float*)d_in[2];
    const float* b1  = (const float*)d_in[3];
    const float* W2  = (const float*)d_in[4];
    const float* b2  = (const float*)d_in[5];
    float* out = (float*)d_out;

    int n = in_sizes[0] / D;
    int e = in_sizes[1] / 2;
    if (n > MAXN) n = MAXN;
    if (e > MAXE) e = MAXE;

    cudaFuncSetAttribute(k_fused, cudaFuncAttributeMaxDynamicSharedMemorySize,
                         SM_TOTAL_F * (int)sizeof(float));

    k_init<<<(n + 255) / 256, 256>>>(n);
    k_count<<<(e + 255) / 256, 256>>>((const int2*)adj, e);
    k_scan<<<1, 1024>>>(n);
    k_scatter<<<(e + 255) / 256, 256>>>((const int2*)adj, e);

    k_fused<<<(n + 63) / 64, 256, SM_TOTAL_F * sizeof(float)>>>(h, W1, b1, W2, n);
    k_agg2_softmax<<<(n * 32 + 255) / 256, 256>>>(b2, out, n);
}

// round 6
// speedup vs baseline: 1.4920x; 1.4541x over previous
#include <cuda_runtime.h>
#include <cuda_bf16.h>
#include <math.h>

#define MAXN 100000
#define MAXE 1200000
#define D    64
#define HID  128
#define C    40
#define NB   ((MAXN + 255) / 256)   // 391 scan blocks

// ---------------- device scratch ----------------
__device__ int   d_deg[MAXN];
__device__ int   d_cursor[MAXN];
__device__ int   d_rowptr[MAXN + 1];
__device__ int   d_col[MAXE];
__device__ int   d_bsum[NB];
__device__ int   d_boff[NB];
__device__ __align__(16) float d_y[(size_t)MAXN * C];

// ---------------- CSR build ----------------
__global__ void k_init(int n) {
    int i = blockIdx.x * blockDim.x + threadIdx.x;
    if (i < n) { d_deg[i] = 0; d_cursor[i] = 0; }
}

__global__ void k_count(const int2* __restrict__ adj, int e) {
    int i = blockIdx.x * blockDim.x + threadIdx.x;
    if (i < e) atomicAdd(&d_deg[adj[i].y], 1);
}

// S1: per-block exclusive scan of 256 contiguous degrees (coalesced)
__global__ void k_scan1(int n) {
    __shared__ int sh[256];
    int t = threadIdx.x;
    int i = blockIdx.x * 256 + t;
    int v = (i < n) ? d_deg[i] : 0;
    sh[t] = v;
    __syncthreads();
#pragma unroll
    for (int off = 1; off < 256; off <<= 1) {
        int add = (t >= off) ? sh[t - off] : 0;
        __syncthreads();
        sh[t] += add;
        __syncthreads();
    }
    if (i < n) d_rowptr[i] = sh[t] - v;      // exclusive, block-local
    if (t == 255) d_bsum[blockIdx.x] = sh[255];
}

// S2: scan block sums (single small block)
__global__ void k_scan2(int nb, int n) {
    __shared__ int sh[512];
    int t = threadIdx.x;
    int v = (t < nb) ? d_bsum[t] : 0;
    sh[t] = v;
    __syncthreads();
#pragma unroll
    for (int off = 1; off < 512; off <<= 1) {
        int add = (t >= off) ? sh[t - off] : 0;
        __syncthreads();
        sh[t] += add;
        __syncthreads();
    }
    if (t < nb) d_boff[t] = sh[t] - v;       // exclusive
    if (t == nb - 1) d_rowptr[n] = sh[t];    // total edge count
}

// S3: add block offsets (coalesced)
__global__ void k_scan3(int n) {
    int i = blockIdx.x * 256 + threadIdx.x;
    if (i < n) d_rowptr[i] += d_boff[blockIdx.x];
}

__global__ void k_scatter(const int2* __restrict__ adj, int e) {
    int i = blockIdx.x * blockDim.x + threadIdx.x;
    if (i < e) {
        int2 ed = adj[i];
        int p = atomicAdd(&d_cursor[ed.y], 1);
        d_col[d_rowptr[ed.y] + p] = ed.x;
    }
}

// ---------------- fused: agg1 + GEMM1 + ReLU + GEMM2 -> d_y ----------------
#define SM_W1 0
#define SM_W2 8192
#define SM_AT 13312
#define SM_X  17664
#define SM_TOTAL_F 25984   // 103936 bytes

__global__ void __launch_bounds__(256) k_fused(const float* __restrict__ h,
                                               const float* __restrict__ W1,
                                               const float* __restrict__ b1,
                                               const float* __restrict__ W2,
                                               int n) {
    extern __shared__ float smem[];
    float* sW1 = smem + SM_W1;
    float* sW2 = smem + SM_W2;
    float* sAT = smem + SM_AT;   // [k][node] stride 68
    float* sX  = smem + SM_X;    // [hid][node] stride 65

    int tid = threadIdx.x;
    int node0 = blockIdx.x * 64;

    {
        const float4* W4 = (const float4*)W1;
        float4* s4 = (float4*)sW1;
#pragma unroll
        for (int i = 0; i < 8; i++) s4[tid + i * 256] = W4[tid + i * 256];
        const float4* V4 = (const float4*)W2;
        float4* t4 = (float4*)sW2;
#pragma unroll
        for (int i = 0; i < 5; i++) t4[tid + i * 256] = V4[tid + i * 256];
    }

    // ---- phase 0: gather-aggregate; half-warp x float4 ----
    {
        int w = tid >> 5, lane = tid & 31;
        int half = lane >> 4;
        int q = lane & 15;
        const float4* h4 = (const float4*)h;
#pragma unroll
        for (int ii = 0; ii < 8; ii++) {
            int nodeL = w * 8 + ii;
            int gn = node0 + nodeL;
            float4 acc = make_float4(0.f, 0.f, 0.f, 0.f);
            if (gn < n) {
                if (half == 0) acc = h4[(size_t)gn * 16 + q];
                int beg = d_rowptr[gn], end = d_rowptr[gn + 1];
                int j = beg;
                for (; j + 3 < end; j += 4) {
                    int s0 = d_col[j + half];
                    int s1 = d_col[j + 2 + half];
                    float4 v0 = h4[(size_t)s0 * 16 + q];
                    float4 v1 = h4[(size_t)s1 * 16 + q];
                    acc.x += v0.x + v1.x;
                    acc.y += v0.y + v1.y;
                    acc.z += v0.z + v1.z;
                    acc.w += v0.w + v1.w;
                }
                if (j + 1 < end) {
                    int s = d_col[j + half];
                    float4 v = h4[(size_t)s * 16 + q];
                    acc.x += v.x; acc.y += v.y; acc.z += v.z; acc.w += v.w;
                    j += 2;
                }
                if (j < end && half == 0) {
                    int s = d_col[j];
                    float4 v = h4[(size_t)s * 16 + q];
                    acc.x += v.x; acc.y += v.y; acc.z += v.z; acc.w += v.w;
                }
            }
            acc.x += __shfl_xor_sync(0xffffffffu, acc.x, 16);
            acc.y += __shfl_xor_sync(0xffffffffu, acc.y, 16);
            acc.z += __shfl_xor_sync(0xffffffffu, acc.z, 16);
            acc.w += __shfl_xor_sync(0xffffffffu, acc.w, 16);
            if (half == 0) {
                sAT[(4 * q + 0) * 68 + nodeL] = acc.x;
                sAT[(4 * q + 1) * 68 + nodeL] = acc.y;
                sAT[(4 * q + 2) * 68 + nodeL] = acc.z;
                sAT[(4 * q + 3) * 68 + nodeL] = acc.w;
            }
        }
    }
    __syncthreads();

    // ---- phase 1: x1 = relu(agg @ W1 + b1) -> sX transposed ----
    {
        int ng = tid & 15;
        int og = tid >> 4;
        float acc[4][8];
#pragma unroll
        for (int i = 0; i < 4; i++)
#pragma unroll
            for (int j = 0; j < 8; j++) acc[i][j] = 0.f;

#pragma unroll
        for (int k = 0; k < D; k++) {
            float4 a4 = *(const float4*)&sAT[k * 68 + ng * 4];
            float av[4] = {a4.x, a4.y, a4.z, a4.w};
            float4 w0 = *(const float4*)&sW1[k * HID + og * 8];
            float4 w1 = *(const float4*)&sW1[k * HID + og * 8 + 4];
            float wv[8] = {w0.x, w0.y, w0.z, w0.w, w1.x, w1.y, w1.z, w1.w};
#pragma unroll
            for (int i = 0; i < 4; i++)
#pragma unroll
                for (int j = 0; j < 8; j++) acc[i][j] += av[i] * wv[j];
        }
        float bb[8];
#pragma unroll
        for (int j = 0; j < 8; j++) bb[j] = b1[og * 8 + j];
#pragma unroll
        for (int i = 0; i < 4; i++)
#pragma unroll
            for (int j = 0; j < 8; j++)
                sX[(og * 8 + j) * 65 + (ng * 4 + i)] = fmaxf(acc[i][j] + bb[j], 0.f);
    }
    __syncthreads();

    // ---- phase 2: y = x1 @ W2 ----
    {
        int og = tid & 7;
        int ng = tid >> 3;
        float acc[2][5];
#pragma unroll
        for (int i = 0; i < 2; i++)
#pragma unroll
            for (int j = 0; j < 5; j++) acc[i][j] = 0.f;

#pragma unroll 8
        for (int k = 0; k < HID; k++) {
            float av[2];
            av[0] = sX[k * 65 + ng * 2];
            av[1] = sX[k * 65 + ng * 2 + 1];
            float wv[5];
#pragma unroll
            for (int j = 0; j < 5; j++) wv[j] = sW2[k * C + og * 5 + j];
#pragma unroll
            for (int i = 0; i < 2; i++)
#pragma unroll
                for (int j = 0; j < 5; j++) acc[i][j] += av[i] * wv[j];
        }
#pragma unroll
        for (int i = 0; i < 2; i++) {
            int gn = node0 + ng * 2 + i;
            if (gn < n) {
#pragma unroll
                for (int j = 0; j < 5; j++)
                    d_y[(size_t)gn * C + og * 5 + j] = acc[i][j];
            }
        }
    }
}

// ---------------- layer-2 aggregation + bias + softmax ----------------
__global__ void k_agg2_softmax(const float* __restrict__ b2, float* __restrict__ out, int n) {
    int w = (blockIdx.x * blockDim.x + threadIdx.x) >> 5;
    int lane = threadIdx.x & 31;
    if (w >= n) return;

    int g = lane / 10;
    int q = lane - g * 10;
    bool act = (lane < 30);
    const float4* Y4 = (const float4*)d_y;

    float4 acc = make_float4(0.f, 0.f, 0.f, 0.f);
    if (act && g == 0) acc = Y4[(size_t)w * 10 + q];

    int beg = d_rowptr[w], end = d_rowptr[w + 1];
    int j = beg;
    for (; j + 5 < end; j += 6) {
        if (act) {
            int s0 = d_col[j + g];
            int s1 = d_col[j + 3 + g];
            float4 v0 = Y4[(size_t)s0 * 10 + q];
            float4 v1 = Y4[(size_t)s1 * 10 + q];
            acc.x += v0.x + v1.x;
            acc.y += v0.y + v1.y;
            acc.z += v0.z + v1.z;
            acc.w += v0.w + v1.w;
        }
    }
    if (j + 2 < end) {
        if (act) {
            int s = d_col[j + g];
            float4 v = Y4[(size_t)s * 10 + q];
            acc.x += v.x; acc.y += v.y; acc.z += v.z; acc.w += v.w;
        }
        j += 3;
    }
    int rem = end - j;
    if (act && g < rem) {
        int s = d_col[j + g];
        float4 v = Y4[(size_t)s * 10 + q];
        acc.x += v.x; acc.y += v.y; acc.z += v.z; acc.w += v.w;
    }

    acc.x += __shfl_sync(0xffffffffu, acc.x, lane + 10) + __shfl_sync(0xffffffffu, acc.x, lane + 20);
    acc.y += __shfl_sync(0xffffffffu, acc.y, lane + 10) + __shfl_sync(0xffffffffu, acc.y, lane + 20);
    acc.z += __shfl_sync(0xffffffffu, acc.z, lane + 10) + __shfl_sync(0xffffffffu, acc.z, lane + 20);
    acc.w += __shfl_sync(0xffffffffu, acc.w, lane + 10) + __shfl_sync(0xffffffffu, acc.w, lane + 20);

    bool own = (lane < 10);
    if (own) {
        acc.x += b2[lane * 4 + 0];
        acc.y += b2[lane * 4 + 1];
        acc.z += b2[lane * 4 + 2];
        acc.w += b2[lane * 4 + 3];
    }
    float m = own ? fmaxf(fmaxf(acc.x, acc.y), fmaxf(acc.z, acc.w)) : -1e30f;
#pragma unroll
    for (int off = 16; off; off >>= 1)
        m = fmaxf(m, __shfl_xor_sync(0xffffffffu, m, off));
    float4 ev;
    ev.x = __expf(acc.x - m);
    ev.y = __expf(acc.y - m);
    ev.z = __expf(acc.z - m);
    ev.w = __expf(acc.w - m);
    float s = own ? (ev.x + ev.y) + (ev.z + ev.w) : 0.f;
#pragma unroll
    for (int off = 16; off; off >>= 1)
        s += __shfl_xor_sync(0xffffffffu, s, off);
    float inv = 1.f / s;
    if (own) {
        float* o = out + (size_t)w * C + lane * 4;
        o[0] = ev.x * inv;
        o[1] = ev.y * inv;
        o[2] = ev.z * inv;
        o[3] = ev.w * inv;
    }
}

// ---------------- launch ----------------
extern "C" void kernel_launch(void* const* d_in, const int* in_sizes, int n_in,
                              void* d_out, int out_size) {
    const float* h   = (const float*)d_in[0];
    const int*   adj = (const int*)d_in[1];
    const float* W1  = (const float*)d_in[2];
    const float* b1  = (const float*)d_in[3];
    const float* W2  = (const float*)d_in[4];
    const float* b2  = (const float*)d_in[5];
    float* out = (float*)d_out;

    int n = in_sizes[0] / D;
    int e = in_sizes[1] / 2;
    if (n > MAXN) n = MAXN;
    if (e > MAXE) e = MAXE;
    int nb = (n + 255) / 256;    // <= 391 < 512

    cudaFuncSetAttribute(k_fused, cudaFuncAttributeMaxDynamicSharedMemorySize,
                         SM_TOTAL_F * (int)sizeof(float));

    k_init<<<(n + 255) / 256, 256>>>(n);
    k_count<<<(e + 255) / 256, 256>>>((const int2*)adj, e);
    k_scan1<<<nb, 256>>>(n);
    k_scan2<<<1, 512>>>(nb, n);
    k_scan3<<<nb, 256>>>(n);
    k_scatter<<<(e + 255) / 256, 256>>>((const int2*)adj, e);

    k_fused<<<(n + 63) / 64, 256, SM_TOTAL_F * sizeof(float)>>>(h, W1, b1, W2, n);
    k_agg2_softmax<<<(n * 32 + 255) / 256, 256>>>(b2, out, n);
}